// round 1
// baseline (speedup 1.0000x reference)
#include <cuda_runtime.h>
#include <cstdint>

// Problem constants (from reference): x (8, 3, 65536) f32 -> out (8, 3, 512) f32
#define BATCHES 8
#define NPTS    65536
#define MOUT    512
#define CLUSTER 8                         // CTAs per batch (one cluster)
#define TPB     256
#define TPBATCH (CLUSTER * TPB)           // 2048 threads per batch
#define PPT     (NPTS / TPBATCH)          // 32 points per thread (register-resident)

// ---- cluster helpers (inline PTX) ----
__device__ __forceinline__ uint32_t cluster_rank() {
    uint32_t r; asm("mov.u32 %0, %%cluster_ctarank;" : "=r"(r)); return r;
}
__device__ __forceinline__ uint32_t smem_u32(const void* p) {
    return (uint32_t)__cvta_generic_to_shared(p);
}
__device__ __forceinline__ void st_cluster_u64(uint32_t local_addr, uint32_t rank,
                                               unsigned long long v) {
    uint32_t r;
    asm volatile("mapa.shared::cluster.u32 %0, %1, %2;" : "=r"(r) : "r"(local_addr), "r"(rank));
    asm volatile("st.shared::cluster.u64 [%0], %1;" :: "r"(r), "l"(v) : "memory");
}
__device__ __forceinline__ void cluster_sync_all() {
    asm volatile("barrier.cluster.arrive.aligned;" ::: "memory");
    asm volatile("barrier.cluster.wait.aligned;"   ::: "memory");
}

__global__ void __launch_bounds__(TPB, 1) __cluster_dims__(CLUSTER, 1, 1)
fps_kernel(const float* __restrict__ x, float* __restrict__ out)
{
    __shared__ unsigned long long s_wkey[TPB / 32];        // per-warp winners
    __shared__ unsigned long long s_cand[2][CLUSTER];      // double-buffered cluster candidates

    const uint32_t rank = cluster_rank();
    const int b    = blockIdx.x / CLUSTER;
    const int tid  = threadIdx.x;
    const int lane = tid & 31;
    const int warp = tid >> 5;
    const int tcl  = (int)rank * TPB + tid;                // 0..2047 within batch

    const float* __restrict__ xb = x + (size_t)b * 3 * NPTS;
    float* __restrict__ ob       = out + (size_t)b * 3 * MOUT;

    // Register-resident points + running min distance
    float px[PPT], py[PPT], pz[PPT], dist[PPT];
#pragma unroll
    for (int k = 0; k < PPT; k++) {
        int g = k * TPBATCH + tcl;                         // coalesced, idx increases with k
        px[k]   = __ldg(xb + g);
        py[k]   = __ldg(xb + NPTS + g);
        pz[k]   = __ldg(xb + 2 * NPTS + g);
        dist[k] = INFINITY;
    }

    // First centroid is point 0 (standard PointNet++ convention)
    float cx = __ldg(xb);
    float cy = __ldg(xb + NPTS);
    float cz = __ldg(xb + 2 * NPTS);
    if (rank == 0 && tid == 0) {
        ob[0]        = cx;
        ob[MOUT]     = cy;
        ob[2 * MOUT] = cz;
    }

    const uint32_t cand_base0 = smem_u32(&s_cand[0][rank]);
    const uint32_t cand_base1 = smem_u32(&s_cand[1][rank]);

    for (int j = 1; j < MOUT; j++) {
        // ---- 1) update dist, track local argmax ----
        // Match reference fp32 arithmetic exactly: no FMA contraction,
        // reduction order (dx^2 + dy^2) + dz^2.
        float best = -1.0f;
        int   bidx = 0;
#pragma unroll
        for (int k = 0; k < PPT; k++) {
            float dx = __fadd_rn(px[k], -cx);
            float dy = __fadd_rn(py[k], -cy);
            float dz = __fadd_rn(pz[k], -cz);
            float d  = __fadd_rn(__fadd_rn(__fmul_rn(dx, dx), __fmul_rn(dy, dy)),
                                 __fmul_rn(dz, dz));
            float nd = fminf(dist[k], d);
            dist[k]  = nd;
            if (nd > best) { best = nd; bidx = k * TPBATCH + tcl; }
        }

        // Packed key: (dist bits << 32) | ~idx  -> max picks largest dist,
        // ties resolved to the LOWEST index (jnp.argmax first-occurrence).
        unsigned long long key =
            ((unsigned long long)__float_as_uint(best) << 32) |
            (unsigned long long)(uint32_t)(~(uint32_t)bidx);

        // ---- 2) warp reduce ----
#pragma unroll
        for (int off = 16; off > 0; off >>= 1) {
            unsigned long long k2 = __shfl_down_sync(0xFFFFFFFFu, key, off);
            if (k2 > key) key = k2;
        }
        if (lane == 0) s_wkey[warp] = key;
        __syncthreads();

        // ---- 3) block reduce (warp 0 over 8 per-warp winners) ----
        if (warp == 0) {
            unsigned long long bk = (lane < (TPB / 32)) ? s_wkey[lane] : 0ULL;
#pragma unroll
            for (int off = 4; off > 0; off >>= 1) {
                unsigned long long k2 = __shfl_down_sync(0xFFFFFFFFu, bk, off);
                if (k2 > bk) bk = k2;
            }
            // ---- 4) leader multicasts block candidate to all ranks ----
            if (lane == 0) {
                uint32_t laddr = (j & 1) ? cand_base1 : cand_base0;
#pragma unroll
                for (int r = 0; r < CLUSTER; r++) st_cluster_u64(laddr, r, bk);
            }
        }

        // ---- 5) cluster barrier (release/acquire orders the DSMEM stores) ----
        cluster_sync_all();

        // ---- 6) every thread picks global winner from 8 local candidates ----
        const unsigned long long* cand = s_cand[j & 1];
        unsigned long long wk = cand[0];
#pragma unroll
        for (int r = 1; r < CLUSTER; r++) {
            unsigned long long c = cand[r];
            if (c > wk) wk = c;
        }
        int widx = (int)(~(uint32_t)wk);

        // ---- 7) fetch winning centroid coords (L2-resident broadcast load) ----
        cx = __ldg(xb + widx);
        cy = __ldg(xb + NPTS + widx);
        cz = __ldg(xb + 2 * NPTS + widx);

        if (rank == 0 && tid == 0) {
            ob[j]            = cx;
            ob[MOUT + j]     = cy;
            ob[2 * MOUT + j] = cz;
        }
    }
}

extern "C" void kernel_launch(void* const* d_in, const int* in_sizes, int n_in,
                              void* d_out, int out_size)
{
    const float* x = (const float*)d_in[0];
    float* out     = (float*)d_out;
    // 8 batches x cluster of 8 CTAs; __cluster_dims__ applies to plain launches.
    fps_kernel<<<BATCHES * CLUSTER, TPB>>>(x, out);
}

// round 5
// speedup vs baseline: 1.1314x; 1.1314x over previous
#include <cuda_runtime.h>
#include <cstdint>

// Problem constants (from reference): x (8, 3, 65536) f32 -> out (8, 3, 512) f32
#define BATCHES 8
#define NPTS    65536
#define MOUT    512
#define CLUSTER 8                         // CTAs per batch (one cluster)
#define TPB     256
#define TPBATCH (CLUSTER * TPB)           // 2048 threads per batch
#define PPT     (NPTS / TPBATCH)          // 32 points per thread (register-resident)
#define PAIRS   (PPT / 2)                 // 16 packed f32x2 pairs

typedef unsigned long long u64;
typedef unsigned int u32;

// ---- cluster helpers (inline PTX) ----
__device__ __forceinline__ u32 cluster_rank() {
    u32 r; asm("mov.u32 %0, %%cluster_ctarank;" : "=r"(r)); return r;
}
__device__ __forceinline__ u32 smem_u32(const void* p) {
    return (u32)__cvta_generic_to_shared(p);
}
__device__ __forceinline__ void st_cluster_u64(u32 local_addr, u32 rank, u64 v) {
    u32 r;
    asm volatile("mapa.shared::cluster.u32 %0, %1, %2;" : "=r"(r) : "r"(local_addr), "r"(rank));
    asm volatile("st.shared::cluster.u64 [%0], %1;" :: "r"(r), "l"(v) : "memory");
}
__device__ __forceinline__ void cluster_sync_all() {
    asm volatile("barrier.cluster.arrive.aligned;" ::: "memory");
    asm volatile("barrier.cluster.wait.aligned;"   ::: "memory");
}
// ---- packed f32x2 math (per-lane IEEE .rn, bit-identical to scalar) ----
__device__ __forceinline__ u64 f2pack(float lo, float hi) {
    u64 r; asm("mov.b64 %0, {%1, %2};" : "=l"(r) : "f"(lo), "f"(hi)); return r;
}
__device__ __forceinline__ void f2unpack(float& lo, float& hi, u64 v) {
    asm("mov.b64 {%0, %1}, %2;" : "=f"(lo), "=f"(hi) : "l"(v));
}
__device__ __forceinline__ u64 f2add(u64 a, u64 b) {
    u64 r; asm("add.rn.f32x2 %0, %1, %2;" : "=l"(r) : "l"(a), "l"(b)); return r;
}
__device__ __forceinline__ u64 f2mul(u64 a, u64 b) {
    u64 r; asm("mul.rn.f32x2 %0, %1, %2;" : "=l"(r) : "l"(a), "l"(b)); return r;
}

__global__ void __launch_bounds__(TPB, 1) __cluster_dims__(CLUSTER, 1, 1)
fps_kernel(const float* __restrict__ x, float* __restrict__ out)
{
    __shared__ u64 s_wkey[TPB / 32];        // per-warp winners
    __shared__ u64 s_cand[2][CLUSTER];      // double-buffered cluster candidates

    const u32 rank = cluster_rank();
    const int b    = blockIdx.x / CLUSTER;
    const int tid  = threadIdx.x;
    const int lane = tid & 31;
    const int warp = tid >> 5;
    const int tcl  = (int)rank * TPB + tid;                // 0..2047 within batch

    const float* __restrict__ xb = x + (size_t)b * 3 * NPTS;
    float* __restrict__ ob       = out + (size_t)b * 3 * MOUT;

    // Register-resident points (packed pairs) + running min distance
    u64 px2[PAIRS], py2[PAIRS], pz2[PAIRS];
    float dist[PPT];
#pragma unroll
    for (int i = 0; i < PAIRS; i++) {
        int k0 = 2 * i, k1 = 2 * i + 1;
        int g0 = k0 * TPBATCH + tcl, g1 = k1 * TPBATCH + tcl;   // coalesced
        px2[i] = f2pack(__ldg(xb + g0),            __ldg(xb + g1));
        py2[i] = f2pack(__ldg(xb + NPTS + g0),     __ldg(xb + NPTS + g1));
        pz2[i] = f2pack(__ldg(xb + 2 * NPTS + g0), __ldg(xb + 2 * NPTS + g1));
        dist[k0] = INFINITY;
        dist[k1] = INFINITY;
    }

    // First centroid is point 0 (standard PointNet++ convention)
    float cx = __ldg(xb);
    float cy = __ldg(xb + NPTS);
    float cz = __ldg(xb + 2 * NPTS);
    if (rank == 0 && tid == 0) {
        ob[0]        = cx;
        ob[MOUT]     = cy;
        ob[2 * MOUT] = cz;
    }

    const u32 cand_base0 = smem_u32(&s_cand[0][rank]);
    const u32 cand_base1 = smem_u32(&s_cand[1][rank]);

    for (int j = 1; j < MOUT; j++) {
        // ---- pass 1: packed distance update. Per-lane .rn arithmetic, same
        //      order as reference: (dx*dx + dy*dy) + dz*dz. Track max only. ----
        u64 ncx = f2pack(-cx, -cx);
        u64 ncy = f2pack(-cy, -cy);
        u64 ncz = f2pack(-cz, -cz);
        float best = -1.0f;
#pragma unroll
        for (int i = 0; i < PAIRS; i++) {
            u64 dx = f2add(px2[i], ncx);
            u64 dy = f2add(py2[i], ncy);
            u64 dz = f2add(pz2[i], ncz);
            u64 s  = f2add(f2mul(dx, dx), f2mul(dy, dy));
            u64 dd = f2add(s, f2mul(dz, dz));
            float e0, e1;
            f2unpack(e0, e1, dd);
            float n0 = fminf(dist[2 * i],     e0);
            float n1 = fminf(dist[2 * i + 1], e1);
            dist[2 * i]     = n0;
            dist[2 * i + 1] = n1;
            best = fmaxf(best, fmaxf(n0, n1));
        }

        // ---- pass 2: min k among dist[k]==best (first-occurrence argmax) ----
        int kb = 0x7FFFFFFF;
#pragma unroll
        for (int k = 0; k < PPT; k++) {
            if (dist[k] == best) kb = min(kb, k);
        }
        int bidx = kb * TPBATCH + tcl;

        // Packed key: (dist bits << 32) | ~idx  -> max picks largest dist,
        // ties resolved to the LOWEST index (jnp.argmax first-occurrence).
        u64 key = ((u64)__float_as_uint(best) << 32) |
                  (u64)(u32)(~(u32)bidx);

        // ---- warp reduce ----
#pragma unroll
        for (int off = 16; off > 0; off >>= 1) {
            u64 k2 = __shfl_down_sync(0xFFFFFFFFu, key, off);
            if (k2 > key) key = k2;
        }
        if (lane == 0) s_wkey[warp] = key;
        __syncthreads();

        // ---- block reduce (warp 0 over 8 per-warp winners) ----
        if (warp == 0) {
            u64 bk = (lane < (TPB / 32)) ? s_wkey[lane] : 0ULL;
#pragma unroll
            for (int off = 4; off > 0; off >>= 1) {
                u64 k2 = __shfl_down_sync(0xFFFFFFFFu, bk, off);
                if (k2 > bk) bk = k2;
            }
            // ---- leader multicasts block candidate to all ranks ----
            if (lane == 0) {
                u32 laddr = (j & 1) ? cand_base1 : cand_base0;
#pragma unroll
                for (int r = 0; r < CLUSTER; r++) st_cluster_u64(laddr, r, bk);
            }
        }

        // ---- cluster barrier (release/acquire orders the DSMEM stores) ----
        cluster_sync_all();

        // ---- every thread picks global winner from 8 local candidates ----
        const u64* cand = s_cand[j & 1];
        u64 wk = cand[0];
#pragma unroll
        for (int r = 1; r < CLUSTER; r++) {
            u64 c = cand[r];
            if (c > wk) wk = c;
        }
        int widx = (int)(~(u32)wk);

        // ---- fetch winning centroid coords (L2-resident broadcast load) ----
        cx = __ldg(xb + widx);
        cy = __ldg(xb + NPTS + widx);
        cz = __ldg(xb + 2 * NPTS + widx);

        if (rank == 0 && tid == 0) {
            ob[j]            = cx;
            ob[MOUT + j]     = cy;
            ob[2 * MOUT + j] = cz;
        }
    }
}

extern "C" void kernel_launch(void* const* d_in, const int* in_sizes, int n_in,
                              void* d_out, int out_size)
{
    const float* x = (const float*)d_in[0];
    float* out     = (float*)d_out;
    // 8 batches x cluster of 8 CTAs; __cluster_dims__ applies to plain launches.
    fps_kernel<<<BATCHES * CLUSTER, TPB>>>(x, out);
}